// round 13
// baseline (speedup 1.0000x reference)
#include <cuda_runtime.h>
#include <cuda_bf16.h>
#include <math.h>
#include <stdint.h>

#define B     128
#define H     2048
#define E     64
#define I     768
#define TWO_I 1536
#define TOPK  8

#define SAW   40        // smem row stride in bf16 elems (80 bytes: odd multiple of 16B -> conflict-free ldmatrix)
#define SAWB  80        // bytes

// -------- device-global scratch (no allocations allowed) --------
__device__ float g_routing[B * E];
__device__ int   g_count[E];
__device__ int   g_tokens[E * B];
__device__ float g_inter[(size_t)E * B * I];     // silu(g)*u (~25 MB)

// ======================= helpers =======================
__device__ __forceinline__ uint32_t smem_u32(const void* p) {
    uint32_t a;
    asm("{ .reg .u64 t; cvta.to.shared.u64 t, %1; cvt.u32.u64 %0, t; }" : "=r"(a) : "l"(p));
    return a;
}
__device__ __forceinline__ void ldsm4(uint32_t* r, uint32_t a) {
    asm volatile("ldmatrix.sync.aligned.m8n8.x4.shared.b16 {%0,%1,%2,%3}, [%4];"
        : "=r"(r[0]), "=r"(r[1]), "=r"(r[2]), "=r"(r[3]) : "r"(a));
}
__device__ __forceinline__ void mma_bf16(float* d, const uint32_t* a, const uint32_t* b) {
    asm volatile("mma.sync.aligned.m16n8k16.row.col.f32.bf16.bf16.f32 "
        "{%0,%1,%2,%3}, {%4,%5,%6,%7}, {%8,%9}, {%0,%1,%2,%3};"
        : "+f"(d[0]), "+f"(d[1]), "+f"(d[2]), "+f"(d[3])
        : "r"(a[0]), "r"(a[1]), "r"(a[2]), "r"(a[3]), "r"(b[0]), "r"(b[1]));
}
// split fp32x4 -> hi/lo bf16x2 words (low half of each b32 = lower-k element)
__device__ __forceinline__ void cvt_split(float4 v, uint32_t& h01, uint32_t& h23,
                                          uint32_t& l01, uint32_t& l23) {
    asm("cvt.rn.bf16x2.f32 %0, %1, %2;" : "=r"(h01) : "f"(v.y), "f"(v.x));
    asm("cvt.rn.bf16x2.f32 %0, %1, %2;" : "=r"(h23) : "f"(v.w), "f"(v.z));
    float r0 = v.x - __uint_as_float(h01 << 16);
    float r1 = v.y - __uint_as_float(h01 & 0xffff0000u);
    float r2 = v.z - __uint_as_float(h23 << 16);
    float r3 = v.w - __uint_as_float(h23 & 0xffff0000u);
    asm("cvt.rn.bf16x2.f32 %0, %1, %2;" : "=r"(l01) : "f"(r1), "f"(r0));
    asm("cvt.rn.bf16x2.f32 %0, %1, %2;" : "=r"(l23) : "f"(r3), "f"(r2));
}
__device__ __forceinline__ void sts2(uint32_t addr, uint32_t a, uint32_t b) {
    asm volatile("st.shared.v2.b32 [%0], {%1, %2};" :: "r"(addr), "r"(a), "r"(b));
}

// ============================================================================
// Kernel 0: zero output + counters
// ============================================================================
__global__ void k_zero(float* __restrict__ out) {
    int idx = blockIdx.x * blockDim.x + threadIdx.x;
    if (idx < B * H) out[idx] = 0.f;
    if (idx < E) g_count[idx] = 0;
}

// ============================================================================
// Kernel 1: routing (proven)
// ============================================================================
__global__ void k_route(const float* __restrict__ x, const float* __restrict__ gw) {
    int b = blockIdx.x, tid = threadIdx.x, warp = tid >> 5, lane = tid & 31;
    __shared__ float sl[E];
    const float4* xr = (const float4*)(x + (size_t)b * H);
    for (int j = 0; j < 8; ++j) {
        int e = warp * 8 + j;
        const float4* gr = (const float4*)(gw + (size_t)e * H);
        float acc = 0.f;
        for (int t = lane; t < H / 4; t += 32) {
            float4 xv = xr[t], gv = gr[t];
            acc += xv.x * gv.x + xv.y * gv.y + xv.z * gv.z + xv.w * gv.w;
        }
        #pragma unroll
        for (int o = 16; o > 0; o >>= 1) acc += __shfl_xor_sync(0xffffffffu, acc, o);
        if (lane == 0) sl[e] = acc;
    }
    __syncthreads();
    if (tid == 0) {
        float m = sl[0];
        #pragma unroll
        for (int e = 1; e < E; ++e) m = fmaxf(m, sl[e]);
        float p[E];
        #pragma unroll
        for (int e = 0; e < E; ++e) p[e] = expf(sl[e] - m);
        int sel[TOPK]; float val[TOPK]; float ssum = 0.f;
        for (int k = 0; k < TOPK; ++k) {
            int best = 0; float bv = -1.f;
            for (int e = 0; e < E; ++e) if (p[e] > bv) { bv = p[e]; best = e; }
            sel[k] = best; val[k] = bv; ssum += bv; p[best] = -2.f;
        }
        for (int k = 0; k < TOPK; ++k) {
            int e = sel[k];
            g_routing[b * E + e] = val[k] / ssum;
            int pos = atomicAdd(&g_count[e], 1);
            g_tokens[e * B + pos] = b;
        }
    }
}

// ============================================================================
// HMMA grouped GEMM, phase A (FUSED): A-tile = [64 gate rows | 64 up rows],
// epilogue computes silu(gate)*up through smem exchange, writes g_inter
// coalesced. Grid (I/64=12, E, 4). 128 threads = 4 warps.
// ============================================================================
__global__ void __launch_bounds__(128)
k_mma_up(const float* __restrict__ x, const float* __restrict__ w1) {
    int e = blockIdx.y, cnt = g_count[e];
    int m0 = blockIdx.z * 32;
    if (m0 >= cnt) return;
    int n0g = blockIdx.x * 64;           // gate/up row base within I
    int tid = threadIdx.x, wid = tid >> 5, lid = tid & 31;

    __shared__ __align__(16) uint16_t Ahi[128 * SAW], Alo[128 * SAW];
    __shared__ __align__(16) uint16_t Bhi[32 * SAW],  Blo[32 * SAW];
    __shared__ float C[128][33];
    __shared__ int toks[32];

    if (tid < 32) toks[tid] = (m0 + tid < cnt) ? g_tokens[e * B + m0 + tid] : -1;
    __syncthreads();

    // staging: thread -> rows {rs, rs+32, rs+64, rs+96}; smem rows 0..63 = gate, 64..127 = up
    int rs = tid >> 2;            // 0..31
    int c4 = tid & 3;             // 0..3
    const float* wgate = w1 + ((size_t)e * TWO_I + n0g) * H + 4 * c4;
    const float* wup   = w1 + ((size_t)e * TWO_I + I + n0g) * H + 4 * c4;
    const float* wptr[4] = {
        wgate + (size_t)rs * H,  wgate + (size_t)(rs + 32) * H,
        wup   + (size_t)rs * H,  wup   + (size_t)(rs + 32) * H
    };
    int tk = toks[rs];
    const float* xb = x + (size_t)(tk >= 0 ? tk : 0) * H + 4 * c4;

    uint32_t aAh = smem_u32(Ahi), aAl = smem_u32(Alo);
    uint32_t aBh = smem_u32(Bhi), aBl = smem_u32(Blo);
    uint32_t stA = (uint32_t)rs * SAWB + (uint32_t)c4 * 8;

    // ldmatrix lane addresses
    int arow  = wid * 32 + (lid & 15);
    int akoff = (lid >> 4) * 16;
    uint32_t adAh0 = aAh + (uint32_t)arow * SAWB + akoff;
    uint32_t adAh1 = adAh0 + 16 * SAWB;
    uint32_t adAl0 = aAl + (uint32_t)arow * SAWB + akoff;
    uint32_t adAl1 = adAl0 + 16 * SAWB;
    int btok = (((lid >> 4) & 1) << 3) + (lid & 7);
    int bkoff = ((lid >> 3) & 1) * 16;
    uint32_t adBh0 = aBh + (uint32_t)btok * SAWB + bkoff;
    uint32_t adBh1 = adBh0 + 16 * SAWB;
    uint32_t adBl0 = aBl + (uint32_t)btok * SAWB + bkoff;
    uint32_t adBl1 = adBl0 + 16 * SAWB;

    float acc[2][4][4];
    #pragma unroll
    for (int i = 0; i < 2; ++i)
        #pragma unroll
        for (int j = 0; j < 4; ++j)
            #pragma unroll
            for (int r = 0; r < 4; ++r) acc[i][j][r] = 0.f;

    // prefetch chunk 0
    float4 va[4], vb;
    #pragma unroll
    for (int r = 0; r < 4; ++r) va[r] = *(const float4*)(wptr[r]);
    vb = (tk >= 0) ? *(const float4*)xb : make_float4(0.f, 0.f, 0.f, 0.f);

    const int NC = H / 16;        // 128
    for (int c = 0; c < NC; ++c) {
        __syncthreads();
        #pragma unroll
        for (int r = 0; r < 4; ++r) {
            uint32_t h01, h23, l01, l23;
            cvt_split(va[r], h01, h23, l01, l23);
            uint32_t off = stA + (uint32_t)(32 * r) * SAWB;
            sts2(aAh + off, h01, h23);
            sts2(aAl + off, l01, l23);
        }
        {
            uint32_t h01, h23, l01, l23;
            cvt_split(vb, h01, h23, l01, l23);
            sts2(aBh + stA, h01, h23);
            sts2(aBl + stA, l01, l23);
        }
        __syncthreads();

        if (c + 1 < NC) {
            int k0 = (c + 1) * 16;
            #pragma unroll
            for (int r = 0; r < 4; ++r)
                va[r] = *(const float4*)(wptr[r] + k0);
            vb = (tk >= 0) ? *(const float4*)(xb + k0) : make_float4(0.f, 0.f, 0.f, 0.f);
        }

        uint32_t ah0[4], ah1[4], al0[4], al1[4], bh0[4], bh1[4], bl0[4], bl1[4];
        ldsm4(ah0, adAh0); ldsm4(ah1, adAh1);
        ldsm4(al0, adAl0); ldsm4(al1, adAl1);
        ldsm4(bh0, adBh0); ldsm4(bh1, adBh1);
        ldsm4(bl0, adBl0); ldsm4(bl1, adBl1);

        // hi*hi
        mma_bf16(acc[0][0], ah0, &bh0[0]); mma_bf16(acc[0][1], ah0, &bh0[2]);
        mma_bf16(acc[0][2], ah0, &bh1[0]); mma_bf16(acc[0][3], ah0, &bh1[2]);
        mma_bf16(acc[1][0], ah1, &bh0[0]); mma_bf16(acc[1][1], ah1, &bh0[2]);
        mma_bf16(acc[1][2], ah1, &bh1[0]); mma_bf16(acc[1][3], ah1, &bh1[2]);
        // hi*lo
        mma_bf16(acc[0][0], ah0, &bl0[0]); mma_bf16(acc[0][1], ah0, &bl0[2]);
        mma_bf16(acc[0][2], ah0, &bl1[0]); mma_bf16(acc[0][3], ah0, &bl1[2]);
        mma_bf16(acc[1][0], ah1, &bl0[0]); mma_bf16(acc[1][1], ah1, &bl0[2]);
        mma_bf16(acc[1][2], ah1, &bl1[0]); mma_bf16(acc[1][3], ah1, &bl1[2]);
        // lo*hi
        mma_bf16(acc[0][0], al0, &bh0[0]); mma_bf16(acc[0][1], al0, &bh0[2]);
        mma_bf16(acc[0][2], al0, &bh1[0]); mma_bf16(acc[0][3], al0, &bh1[2]);
        mma_bf16(acc[1][0], al1, &bh0[0]); mma_bf16(acc[1][1], al1, &bh0[2]);
        mma_bf16(acc[1][2], al1, &bh1[0]); mma_bf16(acc[1][3], al1, &bh1[2]);
    }

    // epilogue: stage C[row][col], then silu(gate)*up -> g_inter (coalesced)
    int l4 = lid >> 2, l2 = (lid & 3) * 2;
    #pragma unroll
    for (int mt = 0; mt < 2; ++mt)
        #pragma unroll
        for (int nt = 0; nt < 4; ++nt)
            #pragma unroll
            for (int r = 0; r < 4; ++r) {
                int row = wid * 32 + mt * 16 + l4 + (r >> 1) * 8;
                int col = nt * 8 + l2 + (r & 1);
                C[row][col] = acc[mt][nt][r];
            }
    __syncthreads();

    int vcols = min(32, cnt - m0);
    #pragma unroll
    for (int it = 0; it < 16; ++it) {
        int idx = tid + it * 128;
        int col = idx >> 6;          // slot 0..31
        int row = idx & 63;          // i offset 0..63
        if (col < vcols) {
            float g = C[row][col];
            float u = C[row + 64][col];
            g_inter[((size_t)e * B + m0 + col) * I + n0g + row] =
                (g / (1.f + expf(-g))) * u;
        }
    }
}

// ============================================================================
// HMMA grouped GEMM, phase B: out[token] += rw * (w2[e] @ inter[slot])
// Grid (16, E, 4). K = I = 768, chunks of 16.
// ============================================================================
__global__ void __launch_bounds__(128)
k_mma_down(const float* __restrict__ w2, float* __restrict__ out) {
    int e = blockIdx.y, cnt = g_count[e];
    int m0 = blockIdx.z * 32;
    if (m0 >= cnt) return;
    int n0 = blockIdx.x * 128;
    int tid = threadIdx.x, wid = tid >> 5, lid = tid & 31;

    __shared__ __align__(16) uint16_t Ahi[128 * SAW], Alo[128 * SAW];
    __shared__ __align__(16) uint16_t Bhi[32 * SAW],  Blo[32 * SAW];
    __shared__ int   toks[32];
    __shared__ float rw[32];

    if (tid < 32) {
        int t = (m0 + tid < cnt) ? g_tokens[e * B + m0 + tid] : -1;
        toks[tid] = t;
        rw[tid]   = (t >= 0) ? g_routing[t * E + e] : 0.f;
    }
    __syncthreads();

    int rs = tid >> 2;
    int c4 = tid & 3;
    const float* wb = w2 + (size_t)e * H * I + (size_t)(n0 + rs) * I + 4 * c4;
    bool bval = (m0 + rs) < cnt;
    const float* ib = g_inter + ((size_t)e * B + m0 + rs) * I + 4 * c4;

    uint32_t aAh = smem_u32(Ahi), aAl = smem_u32(Alo);
    uint32_t aBh = smem_u32(Bhi), aBl = smem_u32(Blo);
    uint32_t stA = (uint32_t)rs * SAWB + (uint32_t)c4 * 8;

    int arow  = wid * 32 + (lid & 15);
    int akoff = (lid >> 4) * 16;
    uint32_t adAh0 = aAh + (uint32_t)arow * SAWB + akoff;
    uint32_t adAh1 = adAh0 + 16 * SAWB;
    uint32_t adAl0 = aAl + (uint32_t)arow * SAWB + akoff;
    uint32_t adAl1 = adAl0 + 16 * SAWB;
    int btok = (((lid >> 4) & 1) << 3) + (lid & 7);
    int bkoff = ((lid >> 3) & 1) * 16;
    uint32_t adBh0 = aBh + (uint32_t)btok * SAWB + bkoff;
    uint32_t adBh1 = adBh0 + 16 * SAWB;
    uint32_t adBl0 = aBl + (uint32_t)btok * SAWB + bkoff;
    uint32_t adBl1 = adBl0 + 16 * SAWB;

    float acc[2][4][4];
    #pragma unroll
    for (int i = 0; i < 2; ++i)
        #pragma unroll
        for (int j = 0; j < 4; ++j)
            #pragma unroll
            for (int r = 0; r < 4; ++r) acc[i][j][r] = 0.f;

    float4 va[4], vb;
    #pragma unroll
    for (int r = 0; r < 4; ++r) va[r] = *(const float4*)(wb + (size_t)(32 * r) * I);
    vb = bval ? *(const float4*)ib : make_float4(0.f, 0.f, 0.f, 0.f);

    const int NC = I / 16;        // 48
    for (int c = 0; c < NC; ++c) {
        __syncthreads();
        #pragma unroll
        for (int r = 0; r < 4; ++r) {
            uint32_t h01, h23, l01, l23;
            cvt_split(va[r], h01, h23, l01, l23);
            uint32_t off = stA + (uint32_t)(32 * r) * SAWB;
            sts2(aAh + off, h01, h23);
            sts2(aAl + off, l01, l23);
        }
        {
            uint32_t h01, h23, l01, l23;
            cvt_split(vb, h01, h23, l01, l23);
            sts2(aBh + stA, h01, h23);
            sts2(aBl + stA, l01, l23);
        }
        __syncthreads();

        if (c + 1 < NC) {
            int k0 = (c + 1) * 16;
            #pragma unroll
            for (int r = 0; r < 4; ++r)
                va[r] = *(const float4*)(wb + (size_t)(32 * r) * I + k0);
            vb = bval ? *(const float4*)(ib + k0) : make_float4(0.f, 0.f, 0.f, 0.f);
        }

        uint32_t ah0[4], ah1[4], al0[4], al1[4], bh0[4], bh1[4], bl0[4], bl1[4];
        ldsm4(ah0, adAh0); ldsm4(ah1, adAh1);
        ldsm4(al0, adAl0); ldsm4(al1, adAl1);
        ldsm4(bh0, adBh0); ldsm4(bh1, adBh1);
        ldsm4(bl0, adBl0); ldsm4(bl1, adBl1);

        mma_bf16(acc[0][0], ah0, &bh0[0]); mma_bf16(acc[0][1], ah0, &bh0[2]);
        mma_bf16(acc[0][2], ah0, &bh1[0]); mma_bf16(acc[0][3], ah0, &bh1[2]);
        mma_bf16(acc[1][0], ah1, &bh0[0]); mma_bf16(acc[1][1], ah1, &bh0[2]);
        mma_bf16(acc[1][2], ah1, &bh1[0]); mma_bf16(acc[1][3], ah1, &bh1[2]);

        mma_bf16(acc[0][0], ah0, &bl0[0]); mma_bf16(acc[0][1], ah0, &bl0[2]);
        mma_bf16(acc[0][2], ah0, &bl1[0]); mma_bf16(acc[0][3], ah0, &bl1[2]);
        mma_bf16(acc[1][0], ah1, &bl0[0]); mma_bf16(acc[1][1], ah1, &bl0[2]);
        mma_bf16(acc[1][2], ah1, &bl1[0]); mma_bf16(acc[1][3], ah1, &bl1[2]);

        mma_bf16(acc[0][0], al0, &bh0[0]); mma_bf16(acc[0][1], al0, &bh0[2]);
        mma_bf16(acc[0][2], al0, &bh1[0]); mma_bf16(acc[0][3], al0, &bh1[2]);
        mma_bf16(acc[1][0], al1, &bh0[0]); mma_bf16(acc[1][1], al1, &bh0[2]);
        mma_bf16(acc[1][2], al1, &bh1[0]); mma_bf16(acc[1][3], al1, &bh1[2]);
    }

    int l4 = lid >> 2, l2 = (lid & 3) * 2;
    #pragma unroll
    for (int mt = 0; mt < 2; ++mt)
        #pragma unroll
        for (int nt = 0; nt < 4; ++nt)
            #pragma unroll
            for (int r = 0; r < 4; ++r) {
                int col = nt * 8 + l2 + (r & 1);
                int t   = toks[col];
                if (t >= 0) {
                    int row = wid * 32 + mt * 16 + l4 + (r >> 1) * 8;
                    atomicAdd(out + (size_t)t * H + n0 + row, rw[col] * acc[mt][nt][r]);
                }
            }
}

// ============================================================================
// Launch
// ============================================================================
extern "C" void kernel_launch(void* const* d_in, const int* in_sizes, int n_in,
                              void* d_out, int out_size) {
    const float* x  = (const float*)d_in[0];   // (128, 2048)
    const float* gw = (const float*)d_in[1];   // (64, 2048)
    const float* w1 = (const float*)d_in[2];   // (64, 1536, 2048)
    const float* w2 = (const float*)d_in[3];   // (64, 2048, 768)
    float* out = (float*)d_out;                // (128, 1, 2048)

    k_zero<<<(B * H + 255) / 256, 256>>>(out);
    k_route<<<B, 256>>>(x, gw);

    dim3 gA(I / 64, E, B / 32);        // (12, 64, 4)
    k_mma_up<<<gA, 128>>>(x, w1);

    dim3 gB(H / 128, E, B / 32);       // (16, 64, 4)
    k_mma_down<<<gB, 128>>>(w2, out);
}

// round 14
// speedup vs baseline: 1.3876x; 1.3876x over previous
#include <cuda_runtime.h>
#include <cuda_bf16.h>
#include <math.h>
#include <stdint.h>

#define B     128
#define H     2048
#define E     64
#define I     768
#define TWO_I 1536
#define TOPK  8

#define KB    32        // K chunk (floats)
#define SAW   40        // smem row stride in bf16 elems (80 B; holds 32 bf16 + pad, conflict-free ldmatrix)
#define SAWB  80        // bytes

// pool layout (bytes): Ahi 0..10240, Alo 10240..20480, Bhi 20480..23040, Blo 23040..25600
#define P_AHI 0
#define P_ALO 10240
#define P_BHI 20480
#define P_BLO 23040
#define P_SZ  25600

// -------- device-global scratch (no allocations allowed) --------
__device__ float g_routing[B * E];
__device__ int   g_count[E];
__device__ int   g_tokens[E * B];
__device__ float g_inter[(size_t)E * B * I];     // silu(g)*u (~25 MB)

// ======================= helpers =======================
__device__ __forceinline__ uint32_t smem_u32(const void* p) {
    uint32_t a;
    asm("{ .reg .u64 t; cvta.to.shared.u64 t, %1; cvt.u32.u64 %0, t; }" : "=r"(a) : "l"(p));
    return a;
}
__device__ __forceinline__ void ldsm4(uint32_t* r, uint32_t a) {
    asm volatile("ldmatrix.sync.aligned.m8n8.x4.shared.b16 {%0,%1,%2,%3}, [%4];"
        : "=r"(r[0]), "=r"(r[1]), "=r"(r[2]), "=r"(r[3]) : "r"(a));
}
__device__ __forceinline__ void mma_bf16(float* d, const uint32_t* a, const uint32_t* b) {
    asm volatile("mma.sync.aligned.m16n8k16.row.col.f32.bf16.bf16.f32 "
        "{%0,%1,%2,%3}, {%4,%5,%6,%7}, {%8,%9}, {%0,%1,%2,%3};"
        : "+f"(d[0]), "+f"(d[1]), "+f"(d[2]), "+f"(d[3])
        : "r"(a[0]), "r"(a[1]), "r"(a[2]), "r"(a[3]), "r"(b[0]), "r"(b[1]));
}
// split fp32x4 -> hi/lo bf16x2 words (low half of each b32 = lower-k element)
__device__ __forceinline__ void cvt_split(float4 v, uint32_t& h01, uint32_t& h23,
                                          uint32_t& l01, uint32_t& l23) {
    asm("cvt.rn.bf16x2.f32 %0, %1, %2;" : "=r"(h01) : "f"(v.y), "f"(v.x));
    asm("cvt.rn.bf16x2.f32 %0, %1, %2;" : "=r"(h23) : "f"(v.w), "f"(v.z));
    float r0 = v.x - __uint_as_float(h01 << 16);
    float r1 = v.y - __uint_as_float(h01 & 0xffff0000u);
    float r2 = v.z - __uint_as_float(h23 << 16);
    float r3 = v.w - __uint_as_float(h23 & 0xffff0000u);
    asm("cvt.rn.bf16x2.f32 %0, %1, %2;" : "=r"(l01) : "f"(r1), "f"(r0));
    asm("cvt.rn.bf16x2.f32 %0, %1, %2;" : "=r"(l23) : "f"(r3), "f"(r2));
}
__device__ __forceinline__ void sts2(uint32_t addr, uint32_t a, uint32_t b) {
    asm volatile("st.shared.v2.b32 [%0], {%1, %2};" :: "r"(addr), "r"(a), "r"(b));
}

// 24 MMAs for one K=16 step, 3-pass hi/lo split
#define MMA_PASSES(ah0, ah1, al0, al1, bh0, bh1, bl0, bl1)                           \
    mma_bf16(acc[0][0], ah0, &bh0[0]); mma_bf16(acc[0][1], ah0, &bh0[2]);            \
    mma_bf16(acc[0][2], ah0, &bh1[0]); mma_bf16(acc[0][3], ah0, &bh1[2]);            \
    mma_bf16(acc[1][0], ah1, &bh0[0]); mma_bf16(acc[1][1], ah1, &bh0[2]);            \
    mma_bf16(acc[1][2], ah1, &bh1[0]); mma_bf16(acc[1][3], ah1, &bh1[2]);            \
    mma_bf16(acc[0][0], ah0, &bl0[0]); mma_bf16(acc[0][1], ah0, &bl0[2]);            \
    mma_bf16(acc[0][2], ah0, &bl1[0]); mma_bf16(acc[0][3], ah0, &bl1[2]);            \
    mma_bf16(acc[1][0], ah1, &bl0[0]); mma_bf16(acc[1][1], ah1, &bl0[2]);            \
    mma_bf16(acc[1][2], ah1, &bl1[0]); mma_bf16(acc[1][3], ah1, &bl1[2]);            \
    mma_bf16(acc[0][0], al0, &bh0[0]); mma_bf16(acc[0][1], al0, &bh0[2]);            \
    mma_bf16(acc[0][2], al0, &bh1[0]); mma_bf16(acc[0][3], al0, &bh1[2]);            \
    mma_bf16(acc[1][0], al1, &bh0[0]); mma_bf16(acc[1][1], al1, &bh0[2]);            \
    mma_bf16(acc[1][2], al1, &bh1[0]); mma_bf16(acc[1][3], al1, &bh1[2]);

// ============================================================================
// Kernel 0: zero output + counters
// ============================================================================
__global__ void k_zero(float* __restrict__ out) {
    int idx = blockIdx.x * blockDim.x + threadIdx.x;
    if (idx < B * H) out[idx] = 0.f;
    if (idx < E) g_count[idx] = 0;
}

// ============================================================================
// Kernel 1: routing (proven)
// ============================================================================
__global__ void k_route(const float* __restrict__ x, const float* __restrict__ gw) {
    int b = blockIdx.x, tid = threadIdx.x, warp = tid >> 5, lane = tid & 31;
    __shared__ float sl[E];
    const float4* xr = (const float4*)(x + (size_t)b * H);
    for (int j = 0; j < 8; ++j) {
        int e = warp * 8 + j;
        const float4* gr = (const float4*)(gw + (size_t)e * H);
        float acc = 0.f;
        for (int t = lane; t < H / 4; t += 32) {
            float4 xv = xr[t], gv = gr[t];
            acc += xv.x * gv.x + xv.y * gv.y + xv.z * gv.z + xv.w * gv.w;
        }
        #pragma unroll
        for (int o = 16; o > 0; o >>= 1) acc += __shfl_xor_sync(0xffffffffu, acc, o);
        if (lane == 0) sl[e] = acc;
    }
    __syncthreads();
    if (tid == 0) {
        float m = sl[0];
        #pragma unroll
        for (int e = 1; e < E; ++e) m = fmaxf(m, sl[e]);
        float p[E];
        #pragma unroll
        for (int e = 0; e < E; ++e) p[e] = expf(sl[e] - m);
        int sel[TOPK]; float val[TOPK]; float ssum = 0.f;
        for (int k = 0; k < TOPK; ++k) {
            int best = 0; float bv = -1.f;
            for (int e = 0; e < E; ++e) if (p[e] > bv) { bv = p[e]; best = e; }
            sel[k] = best; val[k] = bv; ssum += bv; p[best] = -2.f;
        }
        for (int k = 0; k < TOPK; ++k) {
            int e = sel[k];
            g_routing[b * E + e] = val[k] / ssum;
            int pos = atomicAdd(&g_count[e], 1);
            g_tokens[e * B + pos] = b;
        }
    }
}

// ============================================================================
// HMMA grouped GEMM, phase A (fused silu): A-tile = [64 gate | 64 up] rows.
// K chunks of 32 (half the syncs of R12/R13). Epilogue C-buffer ALIASES the
// tile smem pool so occupancy matches R12. Grid (I/64=12, E, 4), 128 thr.
// ============================================================================
__global__ void __launch_bounds__(128)
k_mma_up(const float* __restrict__ x, const float* __restrict__ w1) {
    int e = blockIdx.y, cnt = g_count[e];
    int m0 = blockIdx.z * 32;
    if (m0 >= cnt) return;
    int n0g = blockIdx.x * 64;
    int tid = threadIdx.x, wid = tid >> 5, lid = tid & 31;

    __shared__ __align__(16) char pool[P_SZ];    // tiles, later reused as C[128][33]
    __shared__ int toks[32];

    if (tid < 32) toks[tid] = (m0 + tid < cnt) ? g_tokens[e * B + m0 + tid] : -1;
    __syncthreads();

    int rs = tid >> 2;            // row-in-group 0..31
    int c4 = tid & 3;             // float4 sub-column 0..3
    const float* wgate = w1 + ((size_t)e * TWO_I + n0g) * H + 4 * c4;
    const float* wup   = w1 + ((size_t)e * TWO_I + I + n0g) * H + 4 * c4;
    const float* wptr[4] = {
        wgate + (size_t)rs * H,  wgate + (size_t)(rs + 32) * H,
        wup   + (size_t)rs * H,  wup   + (size_t)(rs + 32) * H
    };
    int tk = toks[rs];
    const float* xb = x + (size_t)(tk >= 0 ? tk : 0) * H + 4 * c4;

    uint32_t pb  = smem_u32(pool);
    uint32_t aAh = pb + P_AHI, aAl = pb + P_ALO;
    uint32_t aBh = pb + P_BHI, aBl = pb + P_BLO;
    uint32_t stA = (uint32_t)rs * SAWB + (uint32_t)c4 * 8;   // float4 #c4 ; #c4+4 at +32B

    int arow  = wid * 32 + (lid & 15);
    int akoff = (lid >> 4) * 16;
    uint32_t adAh0 = aAh + (uint32_t)arow * SAWB + akoff;
    uint32_t adAh1 = adAh0 + 16 * SAWB;
    uint32_t adAl0 = aAl + (uint32_t)arow * SAWB + akoff;
    uint32_t adAl1 = adAl0 + 16 * SAWB;
    int btok = (((lid >> 4) & 1) << 3) + (lid & 7);
    int bkoff = ((lid >> 3) & 1) * 16;
    uint32_t adBh0 = aBh + (uint32_t)btok * SAWB + bkoff;
    uint32_t adBh1 = adBh0 + 16 * SAWB;
    uint32_t adBl0 = aBl + (uint32_t)btok * SAWB + bkoff;
    uint32_t adBl1 = adBl0 + 16 * SAWB;

    float acc[2][4][4];
    #pragma unroll
    for (int i = 0; i < 2; ++i)
        #pragma unroll
        for (int j = 0; j < 4; ++j)
            #pragma unroll
            for (int r = 0; r < 4; ++r) acc[i][j][r] = 0.f;

    // prefetch chunk 0: per thread 4 rows x 2 float4 (cols 4c4, 4c4+16) + B 1 row x 2
    float4 va[8], vb[2];
    #pragma unroll
    for (int r = 0; r < 4; ++r) {
        va[2 * r]     = *(const float4*)(wptr[r]);
        va[2 * r + 1] = *(const float4*)(wptr[r] + 16);
    }
    vb[0] = (tk >= 0) ? *(const float4*)(xb)      : make_float4(0.f, 0.f, 0.f, 0.f);
    vb[1] = (tk >= 0) ? *(const float4*)(xb + 16) : make_float4(0.f, 0.f, 0.f, 0.f);

    const int NC = H / KB;        // 64
    for (int c = 0; c < NC; ++c) {
        __syncthreads();
        #pragma unroll
        for (int r = 0; r < 4; ++r) {
            uint32_t h01, h23, l01, l23;
            uint32_t off = stA + (uint32_t)(32 * r) * SAWB;
            cvt_split(va[2 * r], h01, h23, l01, l23);
            sts2(aAh + off, h01, h23);       sts2(aAl + off, l01, l23);
            cvt_split(va[2 * r + 1], h01, h23, l01, l23);
            sts2(aAh + off + 32, h01, h23);  sts2(aAl + off + 32, l01, l23);
        }
        {
            uint32_t h01, h23, l01, l23;
            cvt_split(vb[0], h01, h23, l01, l23);
            sts2(aBh + stA, h01, h23);       sts2(aBl + stA, l01, l23);
            cvt_split(vb[1], h01, h23, l01, l23);
            sts2(aBh + stA + 32, h01, h23);  sts2(aBl + stA + 32, l01, l23);
        }
        __syncthreads();

        if (c + 1 < NC) {
            int k0 = (c + 1) * KB;
            #pragma unroll
            for (int r = 0; r < 4; ++r) {
                va[2 * r]     = *(const float4*)(wptr[r] + k0);
                va[2 * r + 1] = *(const float4*)(wptr[r] + k0 + 16);
            }
            vb[0] = (tk >= 0) ? *(const float4*)(xb + k0)      : make_float4(0.f,0.f,0.f,0.f);
            vb[1] = (tk >= 0) ? *(const float4*)(xb + k0 + 16) : make_float4(0.f,0.f,0.f,0.f);
        }

        #pragma unroll
        for (int kh = 0; kh < 2; ++kh) {
            uint32_t ko = kh * 32;
            uint32_t ah0[4], ah1[4], al0[4], al1[4], bh0[4], bh1[4], bl0[4], bl1[4];
            ldsm4(ah0, adAh0 + ko); ldsm4(ah1, adAh1 + ko);
            ldsm4(al0, adAl0 + ko); ldsm4(al1, adAl1 + ko);
            ldsm4(bh0, adBh0 + ko); ldsm4(bh1, adBh1 + ko);
            ldsm4(bl0, adBl0 + ko); ldsm4(bl1, adBl1 + ko);
            MMA_PASSES(ah0, ah1, al0, al1, bh0, bh1, bl0, bl1)
        }
    }

    // epilogue: reuse pool as C[128][33]
    __syncthreads();                         // tiles dead
    float (*C)[33] = (float(*)[33])pool;
    int l4 = lid >> 2, l2 = (lid & 3) * 2;
    #pragma unroll
    for (int mt = 0; mt < 2; ++mt)
        #pragma unroll
        for (int nt = 0; nt < 4; ++nt)
            #pragma unroll
            for (int r = 0; r < 4; ++r) {
                int row = wid * 32 + mt * 16 + l4 + (r >> 1) * 8;
                int col = nt * 8 + l2 + (r & 1);
                C[row][col] = acc[mt][nt][r];
            }
    __syncthreads();

    int vcols = min(32, cnt - m0);
    #pragma unroll
    for (int it = 0; it < 16; ++it) {
        int idx = tid + it * 128;
        int col = idx >> 6;          // slot 0..31
        int row = idx & 63;          // i offset 0..63
        if (col < vcols) {
            float g = C[row][col];
            float u = C[row + 64][col];
            g_inter[((size_t)e * B + m0 + col) * I + n0g + row] =
                (g / (1.f + expf(-g))) * u;
        }
    }
}

// ============================================================================
// HMMA grouped GEMM, phase B: out[token] += rw * (w2[e] @ inter[slot])
// Grid (16, E, 4). K = I = 768, chunks of 32 (24 iters).
// ============================================================================
__global__ void __launch_bounds__(128)
k_mma_down(const float* __restrict__ w2, float* __restrict__ out) {
    int e = blockIdx.y, cnt = g_count[e];
    int m0 = blockIdx.z * 32;
    if (m0 >= cnt) return;
    int n0 = blockIdx.x * 128;
    int tid = threadIdx.x, wid = tid >> 5, lid = tid & 31;

    __shared__ __align__(16) char pool[P_SZ];
    __shared__ int   toks[32];
    __shared__ float rw[32];

    if (tid < 32) {
        int t = (m0 + tid < cnt) ? g_tokens[e * B + m0 + tid] : -1;
        toks[tid] = t;
        rw[tid]   = (t >= 0) ? g_routing[t * E + e] : 0.f;
    }
    __syncthreads();

    int rs = tid >> 2;
    int c4 = tid & 3;
    const float* wb = w2 + (size_t)e * H * I + (size_t)(n0 + rs) * I + 4 * c4;
    bool bval = (m0 + rs) < cnt;
    const float* ib = g_inter + ((size_t)e * B + m0 + rs) * I + 4 * c4;

    uint32_t pb  = smem_u32(pool);
    uint32_t aAh = pb + P_AHI, aAl = pb + P_ALO;
    uint32_t aBh = pb + P_BHI, aBl = pb + P_BLO;
    uint32_t stA = (uint32_t)rs * SAWB + (uint32_t)c4 * 8;

    int arow  = wid * 32 + (lid & 15);
    int akoff = (lid >> 4) * 16;
    uint32_t adAh0 = aAh + (uint32_t)arow * SAWB + akoff;
    uint32_t adAh1 = adAh0 + 16 * SAWB;
    uint32_t adAl0 = aAl + (uint32_t)arow * SAWB + akoff;
    uint32_t adAl1 = adAl0 + 16 * SAWB;
    int btok = (((lid >> 4) & 1) << 3) + (lid & 7);
    int bkoff = ((lid >> 3) & 1) * 16;
    uint32_t adBh0 = aBh + (uint32_t)btok * SAWB + bkoff;
    uint32_t adBh1 = adBh0 + 16 * SAWB;
    uint32_t adBl0 = aBl + (uint32_t)btok * SAWB + bkoff;
    uint32_t adBl1 = adBl0 + 16 * SAWB;

    float acc[2][4][4];
    #pragma unroll
    for (int i = 0; i < 2; ++i)
        #pragma unroll
        for (int j = 0; j < 4; ++j)
            #pragma unroll
            for (int r = 0; r < 4; ++r) acc[i][j][r] = 0.f;

    float4 va[8], vb[2];
    #pragma unroll
    for (int r = 0; r < 4; ++r) {
        va[2 * r]     = *(const float4*)(wb + (size_t)(32 * r) * I);
        va[2 * r + 1] = *(const float4*)(wb + (size_t)(32 * r) * I + 16);
    }
    vb[0] = bval ? *(const float4*)(ib)      : make_float4(0.f, 0.f, 0.f, 0.f);
    vb[1] = bval ? *(const float4*)(ib + 16) : make_float4(0.f, 0.f, 0.f, 0.f);

    const int NC = I / KB;        // 24
    for (int c = 0; c < NC; ++c) {
        __syncthreads();
        #pragma unroll
        for (int r = 0; r < 4; ++r) {
            uint32_t h01, h23, l01, l23;
            uint32_t off = stA + (uint32_t)(32 * r) * SAWB;
            cvt_split(va[2 * r], h01, h23, l01, l23);
            sts2(aAh + off, h01, h23);       sts2(aAl + off, l01, l23);
            cvt_split(va[2 * r + 1], h01, h23, l01, l23);
            sts2(aAh + off + 32, h01, h23);  sts2(aAl + off + 32, l01, l23);
        }
        {
            uint32_t h01, h23, l01, l23;
            cvt_split(vb[0], h01, h23, l01, l23);
            sts2(aBh + stA, h01, h23);       sts2(aBl + stA, l01, l23);
            cvt_split(vb[1], h01, h23, l01, l23);
            sts2(aBh + stA + 32, h01, h23);  sts2(aBl + stA + 32, l01, l23);
        }
        __syncthreads();

        if (c + 1 < NC) {
            int k0 = (c + 1) * KB;
            #pragma unroll
            for (int r = 0; r < 4; ++r) {
                va[2 * r]     = *(const float4*)(wb + (size_t)(32 * r) * I + k0);
                va[2 * r + 1] = *(const float4*)(wb + (size_t)(32 * r) * I + k0 + 16);
            }
            vb[0] = bval ? *(const float4*)(ib + k0)      : make_float4(0.f,0.f,0.f,0.f);
            vb[1] = bval ? *(const float4*)(ib + k0 + 16) : make_float4(0.f,0.f,0.f,0.f);
        }

        #pragma unroll
        for (int kh = 0; kh < 2; ++kh) {
            uint32_t ko = kh * 32;
            uint32_t ah0[4], ah1[4], al0[4], al1[4], bh0[4], bh1[4], bl0[4], bl1[4];
            ldsm4(ah0, adAh0 + ko); ldsm4(ah1, adAh1 + ko);
            ldsm4(al0, adAl0 + ko); ldsm4(al1, adAl1 + ko);
            ldsm4(bh0, adBh0 + ko); ldsm4(bh1, adBh1 + ko);
            ldsm4(bl0, adBl0 + ko); ldsm4(bl1, adBl1 + ko);
            MMA_PASSES(ah0, ah1, al0, al1, bh0, bh1, bl0, bl1)
        }
    }

    int l4 = lid >> 2, l2 = (lid & 3) * 2;
    #pragma unroll
    for (int mt = 0; mt < 2; ++mt)
        #pragma unroll
        for (int nt = 0; nt < 4; ++nt)
            #pragma unroll
            for (int r = 0; r < 4; ++r) {
                int col = nt * 8 + l2 + (r & 1);
                int t   = toks[col];
                if (t >= 0) {
                    int row = wid * 32 + mt * 16 + l4 + (r >> 1) * 8;
                    atomicAdd(out + (size_t)t * H + n0 + row, rw[col] * acc[mt][nt][r]);
                }
            }
}

// ============================================================================
// Launch
// ============================================================================
extern "C" void kernel_launch(void* const* d_in, const int* in_sizes, int n_in,
                              void* d_out, int out_size) {
    const float* x  = (const float*)d_in[0];   // (128, 2048)
    const float* gw = (const float*)d_in[1];   // (64, 2048)
    const float* w1 = (const float*)d_in[2];   // (64, 1536, 2048)
    const float* w2 = (const float*)d_in[3];   // (64, 2048, 768)
    float* out = (float*)d_out;                // (128, 1, 2048)

    k_zero<<<(B * H + 255) / 256, 256>>>(out);
    k_route<<<B, 256>>>(x, gw);

    dim3 gA(I / 64, E, B / 32);        // (12, 64, 4)
    k_mma_up<<<gA, 128>>>(x, w1);

    dim3 gB(H / 128, E, B / 32);       // (16, 64, 4)
    k_mma_down<<<gB, 128>>>(w2, out);
}